// round 10
// baseline (speedup 1.0000x reference)
#include <cuda_runtime.h>
#include <cuda_bf16.h>
#include <math.h>

#define N_NODES    500000
#define NUM_GRAPHS 1024

// Scratch (no cudaMalloc allowed). BSS-zeroed at load; self-cleaning per call.
__device__ float g_agg [N_NODES * 4];      // 8 MB, L2-resident
__device__ float g_sums[NUM_GRAPHS * 4];
__device__ float g_cnts[NUM_GRAPHS];

// PDL: wait until predecessor kernel's writes are visible.
__device__ __forceinline__ void pdl_wait() {
    asm volatile("griddepcontrol.wait;" ::: "memory");
}

// ---------------------------------------------------------------------------
// Kernel 1: edge scatter  agg[dst] += x[src]   (R2-optimal: 4 edges/thread)
// Bound by L2 sector-op rate: 2 random 16B ops per edge (gather + red.v4).
// At architectural floor — do not perturb.
// ---------------------------------------------------------------------------
__global__ void __launch_bounds__(256) k_edge(const float4* __restrict__ x,
                                              const int*    __restrict__ src,
                                              const int*    __restrict__ dst,
                                              int E) {
    int q  = blockIdx.x * blockDim.x + threadIdx.x;   // quad index
    int Eq = E >> 2;                                   // full quads

    if (q < Eq) {
        int4 s4 = __ldcs(reinterpret_cast<const int4*>(src) + q);
        int4 d4 = __ldcs(reinterpret_cast<const int4*>(dst) + q);

        float4 v0 = __ldg(x + s4.x);
        float4 v1 = __ldg(x + s4.y);
        float4 v2 = __ldg(x + s4.z);
        float4 v3 = __ldg(x + s4.w);

        asm volatile("red.global.add.v4.f32 [%0], {%1, %2, %3, %4};"
                     :: "l"(&g_agg[(size_t)d4.x * 4]),
                        "f"(v0.x), "f"(v0.y), "f"(v0.z), "f"(v0.w) : "memory");
        asm volatile("red.global.add.v4.f32 [%0], {%1, %2, %3, %4};"
                     :: "l"(&g_agg[(size_t)d4.y * 4]),
                        "f"(v1.x), "f"(v1.y), "f"(v1.z), "f"(v1.w) : "memory");
        asm volatile("red.global.add.v4.f32 [%0], {%1, %2, %3, %4};"
                     :: "l"(&g_agg[(size_t)d4.z * 4]),
                        "f"(v2.x), "f"(v2.y), "f"(v2.z), "f"(v2.w) : "memory");
        asm volatile("red.global.add.v4.f32 [%0], {%1, %2, %3, %4};"
                     :: "l"(&g_agg[(size_t)d4.w * 4]),
                        "f"(v3.x), "f"(v3.y), "f"(v3.z), "f"(v3.w) : "memory");
    } else if (q == Eq) {
        for (int i = Eq * 4; i < E; i++) {
            int s = __ldg(src + i);
            int d = __ldg(dst + i);
            float4 v = __ldg(x + s);
            asm volatile("red.global.add.v4.f32 [%0], {%1, %2, %3, %4};"
                         :: "l"(&g_agg[(size_t)d * 4]),
                            "f"(v.x), "f"(v.y), "f"(v.z), "f"(v.w) : "memory");
        }
    }
}

// ---------------------------------------------------------------------------
// Kernel 2: per-node MLP + pooled sum (one thread per node).
// PDL: weight staging + x/batch loads happen BEFORE griddepcontrol.wait,
// overlapping k_edge's drain; only the g_agg read waits.
// Self-cleaning: zeroes g_agg after consuming it.
// ---------------------------------------------------------------------------
__global__ void __launch_bounds__(256) k_node(const float4* __restrict__ x,
                       const int*    __restrict__ batch,
                       const float*  __restrict__ eps_p,
                       const float*  __restrict__ W1,   // [4,16] row-major
                       const float*  __restrict__ b1,   // [16]
                       const float*  __restrict__ W2,   // [16,4] row-major
                       const float*  __restrict__ b2) { // [4]
    __shared__ float sW1[64], sb1[16], sW2[64], sb2[4];
    __shared__ float seps;
    int t = threadIdx.x;
    if (t < 64)  sW1[t] = W1[t];
    if (t < 16)  sb1[t] = b1[t];
    if (t >= 64 && t < 128) sW2[t - 64] = W2[t - 64];
    if (t >= 128 && t < 132) sb2[t - 128] = b2[t - 128];
    if (t == 132) seps = 1.0f + eps_p[0];

    int i = blockIdx.x * blockDim.x + threadIdx.x;

    // Inputs that do NOT depend on k_edge: prefetch before the PDL wait.
    float4 xv = make_float4(0.f, 0.f, 0.f, 0.f);
    int g = -1;
    if (i < N_NODES) {
        xv = __ldg(x + i);
        g  = __ldg(batch + i);
    }
    __syncthreads();                 // weights staged

    pdl_wait();                      // k_edge's g_agg now visible

    float o0 = 0.f, o1 = 0.f, o2 = 0.f, o3 = 0.f, cnt = 0.f;

    if (i < N_NODES) {
        float4* aggv = reinterpret_cast<float4*>(g_agg);
        float4 av = aggv[i];
        aggv[i] = make_float4(0.f, 0.f, 0.f, 0.f);   // reset for next replay
        float se = seps;
        float h0 = se * xv.x + av.x;
        float h1 = se * xv.y + av.y;
        float h2 = se * xv.z + av.z;
        float h3 = se * xv.w + av.w;

        float out4[4];
        #pragma unroll
        for (int k = 0; k < 4; k++) out4[k] = sb2[k];

        #pragma unroll
        for (int j = 0; j < 16; j++) {
            float tj = sb1[j]
                     + h0 * sW1[0 * 16 + j]
                     + h1 * sW1[1 * 16 + j]
                     + h2 * sW1[2 * 16 + j]
                     + h3 * sW1[3 * 16 + j];
            tj = fmaxf(tj, 0.0f);
            #pragma unroll
            for (int k = 0; k < 4; k++) out4[k] += tj * sW2[j * 4 + k];
        }
        o0 = fmaxf(out4[0], 0.0f);
        o1 = fmaxf(out4[1], 0.0f);
        o2 = fmaxf(out4[2], 0.0f);
        o3 = fmaxf(out4[3], 0.0f);
        cnt = 1.0f;
    }

    unsigned lane = threadIdx.x & 31u;
    int g0 = __shfl_sync(0xFFFFFFFFu, g, 0);

    if (__all_sync(0xFFFFFFFFu, g == g0)) {
        // fast path: whole warp in one graph
        #pragma unroll
        for (int off = 16; off > 0; off >>= 1) {
            o0  += __shfl_xor_sync(0xFFFFFFFFu, o0,  off);
            o1  += __shfl_xor_sync(0xFFFFFFFFu, o1,  off);
            o2  += __shfl_xor_sync(0xFFFFFFFFu, o2,  off);
            o3  += __shfl_xor_sync(0xFFFFFFFFu, o3,  off);
            cnt += __shfl_xor_sync(0xFFFFFFFFu, cnt, off);
        }
        if (lane == 0 && g0 >= 0) {
            atomicAdd(&g_sums[g0 * 4 + 0], o0);
            atomicAdd(&g_sums[g0 * 4 + 1], o1);
            atomicAdd(&g_sums[g0 * 4 + 2], o2);
            atomicAdd(&g_sums[g0 * 4 + 3], o3);
            atomicAdd(&g_cnts[g0], cnt);
        }
    } else {
        // slow path: warp-segmented inclusive scan over sorted ids
        #pragma unroll
        for (int off = 1; off < 32; off <<= 1) {
            int   gg = __shfl_up_sync(0xFFFFFFFFu, g,   off);
            float t0 = __shfl_up_sync(0xFFFFFFFFu, o0,  off);
            float t1 = __shfl_up_sync(0xFFFFFFFFu, o1,  off);
            float t2 = __shfl_up_sync(0xFFFFFFFFu, o2,  off);
            float t3 = __shfl_up_sync(0xFFFFFFFFu, o3,  off);
            float tc = __shfl_up_sync(0xFFFFFFFFu, cnt, off);
            if (lane >= (unsigned)off && gg == g) {
                o0 += t0; o1 += t1; o2 += t2; o3 += t3; cnt += tc;
            }
        }
        int gnext = __shfl_down_sync(0xFFFFFFFFu, g, 1);
        bool last = (lane == 31u) || (gnext != g);
        if (last && g >= 0) {
            atomicAdd(&g_sums[g * 4 + 0], o0);
            atomicAdd(&g_sums[g * 4 + 1], o1);
            atomicAdd(&g_sums[g * 4 + 2], o2);
            atomicAdd(&g_sums[g * 4 + 3], o3);
            atomicAdd(&g_cnts[g], cnt);
        }
    }
}

// ---------------------------------------------------------------------------
// Kernel 3: mean pool + log_softmax; zeroes g_sums/g_cnts after consuming.
// PDL: launch overlaps k_node; waits before reading pools.
// ---------------------------------------------------------------------------
__global__ void k_pool(float* __restrict__ out) {
    int g = blockIdx.x * blockDim.x + threadIdx.x;
    pdl_wait();
    if (g >= NUM_GRAPHS) return;
    float c = fmaxf(g_cnts[g], 1.0f);
    g_cnts[g] = 0.0f;
    float v[4];
    float m = -INFINITY;
    #pragma unroll
    for (int k = 0; k < 4; k++) {
        v[k] = g_sums[g * 4 + k] / c;
        g_sums[g * 4 + k] = 0.0f;
        m = fmaxf(m, v[k]);
    }
    float s = 0.0f;
    #pragma unroll
    for (int k = 0; k < 4; k++) s += expf(v[k] - m);
    float l = m + logf(s);
    #pragma unroll
    for (int k = 0; k < 4; k++) out[g * 4 + k] = v[k] - l;
}

// ---------------------------------------------------------------------------
extern "C" void kernel_launch(void* const* d_in, const int* in_sizes, int n_in,
                              void* d_out, int out_size) {
    const float4* x   = (const float4*)d_in[0];
    const int*    ei  = (const int*)   d_in[1];   // [2, E]
    const int*    bat = (const int*)   d_in[2];
    const float*  eps = (const float*) d_in[3];
    const float*  W1  = (const float*) d_in[4];
    const float*  b1  = (const float*) d_in[5];
    const float*  W2  = (const float*) d_in[6];
    const float*  b2  = (const float*) d_in[7];
    float* out = (float*)d_out;

    int E = in_sizes[1] / 2;
    const int* src = ei;
    const int* dst = ei + E;

    int quads = E / 4 + 1;  // +1 thread for the tail
    k_edge<<<(quads + 255) / 256, 256>>>(x, src, dst, E);

    cudaLaunchAttribute pdl[1];
    pdl[0].id = cudaLaunchAttributeProgrammaticStreamSerialization;
    pdl[0].val.programmaticStreamSerializationAllowed = 1;

    {   // k_node with PDL
        cudaLaunchConfig_t cfg = {};
        cfg.gridDim  = dim3((N_NODES + 255) / 256);
        cfg.blockDim = dim3(256);
        cfg.attrs    = pdl;
        cfg.numAttrs = 1;
        cudaLaunchKernelEx(&cfg, k_node, x, bat, eps, W1, b1, W2, b2);
    }
    {   // k_pool with PDL
        cudaLaunchConfig_t cfg = {};
        cfg.gridDim  = dim3((NUM_GRAPHS + 255) / 256);
        cfg.blockDim = dim3(256);
        cfg.attrs    = pdl;
        cfg.numAttrs = 1;
        cudaLaunchKernelEx(&cfg, k_pool, out);
    }
}

// round 11
// speedup vs baseline: 1.6491x; 1.6491x over previous
#include <cuda_runtime.h>
#include <cuda_bf16.h>
#include <math.h>

#define N_NODES    500000
#define NUM_GRAPHS 1024

// Scratch (no cudaMalloc allowed). BSS-zeroed at load; self-cleaning per call.
__device__ float g_agg [N_NODES * 4];      // 8 MB, L2-resident
__device__ float g_sums[NUM_GRAPHS * 4];
__device__ float g_cnts[NUM_GRAPHS];

// ---------------------------------------------------------------------------
// Kernel 1: edge scatter  agg[dst] += x[src]   (4 edges/thread)
// Bound by L2 sector-op rate. Experiment: __ldcg gathers (L2-only, no L1
// allocation) — expected L1 hit rate ~3%, so skip L1 fill/allocate work.
// ---------------------------------------------------------------------------
__global__ void __launch_bounds__(256) k_edge(const float4* __restrict__ x,
                                              const int*    __restrict__ src,
                                              const int*    __restrict__ dst,
                                              int E) {
    int q  = blockIdx.x * blockDim.x + threadIdx.x;   // quad index
    int Eq = E >> 2;                                   // full quads

    if (q < Eq) {
        int4 s4 = __ldcs(reinterpret_cast<const int4*>(src) + q);
        int4 d4 = __ldcs(reinterpret_cast<const int4*>(dst) + q);

        float4 v0 = __ldcg(x + s4.x);
        float4 v1 = __ldcg(x + s4.y);
        float4 v2 = __ldcg(x + s4.z);
        float4 v3 = __ldcg(x + s4.w);

        asm volatile("red.global.add.v4.f32 [%0], {%1, %2, %3, %4};"
                     :: "l"(&g_agg[(size_t)d4.x * 4]),
                        "f"(v0.x), "f"(v0.y), "f"(v0.z), "f"(v0.w) : "memory");
        asm volatile("red.global.add.v4.f32 [%0], {%1, %2, %3, %4};"
                     :: "l"(&g_agg[(size_t)d4.y * 4]),
                        "f"(v1.x), "f"(v1.y), "f"(v1.z), "f"(v1.w) : "memory");
        asm volatile("red.global.add.v4.f32 [%0], {%1, %2, %3, %4};"
                     :: "l"(&g_agg[(size_t)d4.z * 4]),
                        "f"(v2.x), "f"(v2.y), "f"(v2.z), "f"(v2.w) : "memory");
        asm volatile("red.global.add.v4.f32 [%0], {%1, %2, %3, %4};"
                     :: "l"(&g_agg[(size_t)d4.w * 4]),
                        "f"(v3.x), "f"(v3.y), "f"(v3.z), "f"(v3.w) : "memory");
    } else if (q == Eq) {
        for (int i = Eq * 4; i < E; i++) {
            int s = __ldg(src + i);
            int d = __ldg(dst + i);
            float4 v = __ldcg(x + s);
            asm volatile("red.global.add.v4.f32 [%0], {%1, %2, %3, %4};"
                         :: "l"(&g_agg[(size_t)d * 4]),
                            "f"(v.x), "f"(v.y), "f"(v.z), "f"(v.w) : "memory");
        }
    }
}

// ---------------------------------------------------------------------------
// Kernel 2: per-node MLP + pooled sum (one thread per node).
// Fast path for graph-uniform warps (~93%): butterfly reduce + 1 flush.
// Slow path (boundary/tail warps): warp-segmented scan.
// Self-cleaning: zeroes g_agg after consuming it.
// ---------------------------------------------------------------------------
__global__ void __launch_bounds__(256) k_node(const float4* __restrict__ x,
                       const int*    __restrict__ batch,
                       const float*  __restrict__ eps_p,
                       const float*  __restrict__ W1,   // [4,16] row-major
                       const float*  __restrict__ b1,   // [16]
                       const float*  __restrict__ W2,   // [16,4] row-major
                       const float*  __restrict__ b2) { // [4]
    __shared__ float sW1[64], sb1[16], sW2[64], sb2[4];
    __shared__ float seps;
    int t = threadIdx.x;
    if (t < 64)  sW1[t] = W1[t];
    if (t < 16)  sb1[t] = b1[t];
    if (t >= 64 && t < 128) sW2[t - 64] = W2[t - 64];
    if (t >= 128 && t < 132) sb2[t - 128] = b2[t - 128];
    if (t == 132) seps = 1.0f + eps_p[0];
    __syncthreads();

    int i = blockIdx.x * blockDim.x + threadIdx.x;

    float o0 = 0.f, o1 = 0.f, o2 = 0.f, o3 = 0.f, cnt = 0.f;
    int g = -1;

    if (i < N_NODES) {
        float4 xv = __ldg(x + i);
        float4* aggv = reinterpret_cast<float4*>(g_agg);
        float4 av = aggv[i];
        aggv[i] = make_float4(0.f, 0.f, 0.f, 0.f);   // reset for next replay
        float se = seps;
        float h0 = se * xv.x + av.x;
        float h1 = se * xv.y + av.y;
        float h2 = se * xv.z + av.z;
        float h3 = se * xv.w + av.w;

        float out4[4];
        #pragma unroll
        for (int k = 0; k < 4; k++) out4[k] = sb2[k];

        #pragma unroll
        for (int j = 0; j < 16; j++) {
            float tj = sb1[j]
                     + h0 * sW1[0 * 16 + j]
                     + h1 * sW1[1 * 16 + j]
                     + h2 * sW1[2 * 16 + j]
                     + h3 * sW1[3 * 16 + j];
            tj = fmaxf(tj, 0.0f);
            #pragma unroll
            for (int k = 0; k < 4; k++) out4[k] += tj * sW2[j * 4 + k];
        }
        o0 = fmaxf(out4[0], 0.0f);
        o1 = fmaxf(out4[1], 0.0f);
        o2 = fmaxf(out4[2], 0.0f);
        o3 = fmaxf(out4[3], 0.0f);
        cnt = 1.0f;
        g = __ldg(batch + i);
    }

    unsigned lane = threadIdx.x & 31u;
    int g0 = __shfl_sync(0xFFFFFFFFu, g, 0);

    if (__all_sync(0xFFFFFFFFu, g == g0)) {
        // fast path: whole warp in one graph
        #pragma unroll
        for (int off = 16; off > 0; off >>= 1) {
            o0  += __shfl_xor_sync(0xFFFFFFFFu, o0,  off);
            o1  += __shfl_xor_sync(0xFFFFFFFFu, o1,  off);
            o2  += __shfl_xor_sync(0xFFFFFFFFu, o2,  off);
            o3  += __shfl_xor_sync(0xFFFFFFFFu, o3,  off);
            cnt += __shfl_xor_sync(0xFFFFFFFFu, cnt, off);
        }
        if (lane == 0 && g0 >= 0) {
            atomicAdd(&g_sums[g0 * 4 + 0], o0);
            atomicAdd(&g_sums[g0 * 4 + 1], o1);
            atomicAdd(&g_sums[g0 * 4 + 2], o2);
            atomicAdd(&g_sums[g0 * 4 + 3], o3);
            atomicAdd(&g_cnts[g0], cnt);
        }
    } else {
        // slow path: warp-segmented inclusive scan over sorted ids
        #pragma unroll
        for (int off = 1; off < 32; off <<= 1) {
            int   gg = __shfl_up_sync(0xFFFFFFFFu, g,   off);
            float t0 = __shfl_up_sync(0xFFFFFFFFu, o0,  off);
            float t1 = __shfl_up_sync(0xFFFFFFFFu, o1,  off);
            float t2 = __shfl_up_sync(0xFFFFFFFFu, o2,  off);
            float t3 = __shfl_up_sync(0xFFFFFFFFu, o3,  off);
            float tc = __shfl_up_sync(0xFFFFFFFFu, cnt, off);
            if (lane >= (unsigned)off && gg == g) {
                o0 += t0; o1 += t1; o2 += t2; o3 += t3; cnt += tc;
            }
        }
        int gnext = __shfl_down_sync(0xFFFFFFFFu, g, 1);
        bool last = (lane == 31u) || (gnext != g);
        if (last && g >= 0) {
            atomicAdd(&g_sums[g * 4 + 0], o0);
            atomicAdd(&g_sums[g * 4 + 1], o1);
            atomicAdd(&g_sums[g * 4 + 2], o2);
            atomicAdd(&g_sums[g * 4 + 3], o3);
            atomicAdd(&g_cnts[g], cnt);
        }
    }
}

// ---------------------------------------------------------------------------
// Kernel 3: mean pool + log_softmax; zeroes g_sums/g_cnts after consuming.
// ---------------------------------------------------------------------------
__global__ void k_pool(float* __restrict__ out) {
    int g = blockIdx.x * blockDim.x + threadIdx.x;
    if (g >= NUM_GRAPHS) return;
    float c = fmaxf(g_cnts[g], 1.0f);
    g_cnts[g] = 0.0f;
    float v[4];
    float m = -INFINITY;
    #pragma unroll
    for (int k = 0; k < 4; k++) {
        v[k] = g_sums[g * 4 + k] / c;
        g_sums[g * 4 + k] = 0.0f;
        m = fmaxf(m, v[k]);
    }
    float s = 0.0f;
    #pragma unroll
    for (int k = 0; k < 4; k++) s += expf(v[k] - m);
    float l = m + logf(s);
    #pragma unroll
    for (int k = 0; k < 4; k++) out[g * 4 + k] = v[k] - l;
}

// ---------------------------------------------------------------------------
extern "C" void kernel_launch(void* const* d_in, const int* in_sizes, int n_in,
                              void* d_out, int out_size) {
    const float4* x   = (const float4*)d_in[0];
    const int*    ei  = (const int*)   d_in[1];   // [2, E]
    const int*    bat = (const int*)   d_in[2];
    const float*  eps = (const float*) d_in[3];
    const float*  W1  = (const float*) d_in[4];
    const float*  b1  = (const float*) d_in[5];
    const float*  W2  = (const float*) d_in[6];
    const float*  b2  = (const float*) d_in[7];
    float* out = (float*)d_out;

    int E = in_sizes[1] / 2;
    const int* src = ei;
    const int* dst = ei + E;

    int quads = E / 4 + 1;  // +1 thread for the tail
    k_edge<<<(quads + 255) / 256, 256>>>(x, src, dst, E);
    k_node<<<(N_NODES + 255) / 256, 256>>>(x, bat, eps, W1, b1, W2, b2);
    k_pool<<<(NUM_GRAPHS + 255) / 256, 256>>>(out);
}